// round 8
// baseline (speedup 1.0000x reference)
#include <cuda_runtime.h>
#include <cuda_bf16.h>
#include <cstdint>

// ---------------------------------------------------------------------------
// MHSA: B=8, N=1024, D=768, H=12, HD=64.
// R8: attention SOFTWARE-PIPELINED across key-tiles: S(t+1) MMAs issued
// before exp/PV(t), so tensor pipe stays fed during the softmax chain.
// Q pre-split in gemm_qkv (g_qh/g_ql), staged once in smem, ldsm per tile
// (frees 32 regs, pays for the second S accumulator). 4-stage K/V cp.async.
// GEMMs unchanged from R7. Arithmetic bit-identical (rel_err must match).
// ---------------------------------------------------------------------------

constexpr int CB  = 8;
constexpr int CN  = 1024;
constexpr int CD  = 768;
constexpr int CH  = 12;
constexpr int CHD = 64;
constexpr int CM  = CB * CN;   // 8192
constexpr int BH  = CB * CH;   // 96
constexpr int CD2 = CD * 2;

__device__ __nv_bfloat16 g_qh[BH * CN * CHD], g_ql[BH * CN * CHD];
__device__ __nv_bfloat16 g_kh[BH * CN * CHD], g_kl[BH * CN * CHD];
__device__ __nv_bfloat16 g_vth[BH * CHD * CN], g_vtl[BH * CHD * CN];
__device__ __nv_bfloat16 g_xs[CM * CD2];
__device__ __nv_bfloat16 g_as[CM * CD2];
__device__ __nv_bfloat16 g_wt[4 * CD * CD2];

// ======================= PTX helpers =======================================
__device__ __forceinline__ uint32_t smem_u32(const void* p) {
    uint32_t a;
    asm("{ .reg .u64 t; cvta.to.shared.u64 t, %1; cvt.u32.u64 %0, t; }"
        : "=r"(a) : "l"(p));
    return a;
}
__device__ __forceinline__ void ldsm_x4(uint32_t& r0, uint32_t& r1,
                                        uint32_t& r2, uint32_t& r3,
                                        uint32_t addr) {
    asm volatile("ldmatrix.sync.aligned.m8n8.x4.shared.b16 {%0,%1,%2,%3}, [%4];"
                 : "=r"(r0), "=r"(r1), "=r"(r2), "=r"(r3) : "r"(addr));
}
__device__ __forceinline__ void mma16816(float* c, const uint32_t* a,
                                         uint32_t b0, uint32_t b1) {
    asm volatile(
        "mma.sync.aligned.m16n8k16.row.col.f32.bf16.bf16.f32 "
        "{%0,%1,%2,%3}, {%4,%5,%6,%7}, {%8,%9}, {%0,%1,%2,%3};"
        : "+f"(c[0]), "+f"(c[1]), "+f"(c[2]), "+f"(c[3])
        : "r"(a[0]), "r"(a[1]), "r"(a[2]), "r"(a[3]), "r"(b0), "r"(b1));
}
__device__ __forceinline__ uint32_t packbf(float a, float b) {
    __nv_bfloat162 t = __floats2bfloat162_rn(a, b);
    return *(uint32_t*)&t;
}
__device__ __forceinline__ void packsplit(float x, float y,
                                          uint32_t& h, uint32_t& l) {
    const __nv_bfloat16 hx = __float2bfloat16_rn(x);
    const __nv_bfloat16 hy = __float2bfloat16_rn(y);
    __nv_bfloat162 hp; hp.x = hx; hp.y = hy;
    h = *(uint32_t*)&hp;
    l = packbf(x - __bfloat162float(hx), y - __bfloat162float(hy));
}
__device__ __forceinline__ void splits(float v, __nv_bfloat16& h,
                                       __nv_bfloat16& l) {
    h = __float2bfloat16_rn(v);
    l = __float2bfloat16_rn(v - __bfloat162float(h));
}
__device__ __forceinline__ void cp16(uint32_t dst, const void* src) {
    asm volatile("cp.async.cg.shared.global [%0], [%1], 16;"
                 :: "r"(dst), "l"(src) : "memory");
}
__device__ __forceinline__ void cp_commit() {
    asm volatile("cp.async.commit_group;" ::: "memory");
}
__device__ __forceinline__ void cp_wait2() {
    asm volatile("cp.async.wait_group 2;" ::: "memory");
}
__device__ __forceinline__ void cp_wait1() {
    asm volatile("cp.async.wait_group 1;" ::: "memory");
}
__device__ __forceinline__ void cp_wait0() {
    asm volatile("cp.async.wait_group 0;" ::: "memory");
}

// ---------------------------------------------------------------------------
// xsplit: x fp32 [8192,768] -> g_xs chunked split [row][k16][hi16|lo16]
// ---------------------------------------------------------------------------
__global__ void xsplit_kernel(const float* __restrict__ x)
{
    const int t   = blockIdx.x * 256 + threadIdx.x;
    const int row = t / 192;
    const int k0  = (t % 192) * 4;
    const float4 a = *(const float4*)(x + (size_t)row * CD + k0);
    uint32_t h0, l0, h1, l1;
    packsplit(a.x, a.y, h0, l0);
    packsplit(a.z, a.w, h1, l1);
    const size_t d = (size_t)row * CD2 + (k0 >> 4) * 32 + (k0 & 15);
    *(uint2*)(g_xs + d)      = make_uint2(h0, h1);
    *(uint2*)(g_xs + d + 16) = make_uint2(l0, l1);
}

// ---------------------------------------------------------------------------
// wsplit (4 slots fused)
// ---------------------------------------------------------------------------
__global__ void wsplit_kernel(const float* __restrict__ W0,
                              const float* __restrict__ W1,
                              const float* __restrict__ W2,
                              const float* __restrict__ W3)
{
    const int slot = blockIdx.z;
    const float* __restrict__ W = (slot == 0) ? W0 : (slot == 1) ? W1
                                : (slot == 2) ? W2 : W3;
    __shared__ float t[32][33];
    const int n0 = blockIdx.x * 32;
    const int k0 = blockIdx.y * 32;
    const int tx = threadIdx.x;
    const int ty = threadIdx.y;
#pragma unroll
    for (int i = 0; i < 32; i += 8)
        t[ty + i][tx] = W[(k0 + ty + i) * CD + n0 + tx];
    __syncthreads();
    __nv_bfloat16* dst = g_wt + (size_t)slot * CD * CD2;
#pragma unroll
    for (int i = 0; i < 32; i += 8) {
        const float v = t[tx][ty + i];
        __nv_bfloat16 h, l;
        splits(v, h, l);
        const int k = k0 + tx, n = n0 + ty + i;
        const size_t idx = (size_t)n * CD2 + (k >> 4) * 32 + (k & 15);
        dst[idx]      = h;
        dst[idx + 16] = l;
    }
}

// ---------------------------------------------------------------------------
// Fused QKV GEMM (3-stage, unchanged except slot-0 now writes SPLIT Q).
// ---------------------------------------------------------------------------
constexpr int GSB = 128 * 80;
constexpr int QKV_SMEM = 6 * GSB;

__global__ void __launch_bounds__(256, 2)
gemm_qkv(const float* __restrict__ bq, const float* __restrict__ bk,
         const float* __restrict__ bv)
{
    const int slot = blockIdx.z;
    const __nv_bfloat16* __restrict__ Bg = g_wt + (size_t)slot * CD * CD2;
    const float* __restrict__ bias = (slot == 0) ? bq : (slot == 1) ? bk : bv;

    extern __shared__ __align__(16) char dsm[];
    const uint32_t as_b = smem_u32(dsm);
    const uint32_t bs_b = as_b + 3 * GSB;

    const int tid  = threadIdx.x;
    const int wid  = tid >> 5;
    const int lane = tid & 31;
    const int n0   = blockIdx.x * 128;
    const int m0   = blockIdx.y * 128;
    const int wm   = wid & 3;
    const int wn   = wid >> 2;

    const uint32_t a_base = as_b + (wm * 32 + (lane & 15)) * 80 + (lane >> 4) * 16;
    const uint32_t b_base = bs_b + (wn * 64 + (lane & 7) + ((lane >> 4) << 3)) * 80
                          + ((lane >> 3) & 1) * 16;

    const int srow = tid >> 2;
    const int sj   = (tid & 3) * 16;

    auto issue = [&](int kc, int s) {
#pragma unroll
        for (int u = 0; u < 2; ++u) {
            const int row = srow + 64 * u;
            cp16(as_b + s * GSB + row * 80 + sj,
                 (const char*)g_xs + (size_t)(m0 + row) * 3072 + kc * 64 + sj);
            cp16(bs_b + s * GSB + row * 80 + sj,
                 (const char*)Bg + (size_t)(n0 + row) * 3072 + kc * 64 + sj);
        }
        cp_commit();
    };

    float c[2][8][4];
#pragma unroll
    for (int mi = 0; mi < 2; ++mi)
#pragma unroll
        for (int nf = 0; nf < 8; ++nf)
#pragma unroll
            for (int q = 0; q < 4; ++q) c[mi][nf][q] = 0.f;

    issue(0, 0);
    issue(1, 1);

    for (int kc = 0; kc < 48; ++kc) {
        if (kc < 47) cp_wait1(); else cp_wait0();
        __syncthreads();
        if (kc + 2 < 48) issue(kc + 2, (kc + 2) % 3);
        const uint32_t sb = (kc % 3) * GSB;

        uint32_t ah[2][4], al[2][4];
#pragma unroll
        for (int mi = 0; mi < 2; ++mi) {
            const uint32_t aa = a_base + sb + mi * 16 * 80;
            ldsm_x4(ah[mi][0], ah[mi][1], ah[mi][2], ah[mi][3], aa);
            ldsm_x4(al[mi][0], al[mi][1], al[mi][2], al[mi][3], aa + 32);
        }
#pragma unroll
        for (int nj = 0; nj < 4; ++nj) {
            const uint32_t bb = b_base + sb + nj * 16 * 80;
            uint32_t bh0, bh1, bh2, bh3, bl0, bl1, bl2, bl3;
            ldsm_x4(bh0, bh1, bh2, bh3, bb);
            ldsm_x4(bl0, bl1, bl2, bl3, bb + 32);
#pragma unroll
            for (int mi = 0; mi < 2; ++mi) {
                float* c0 = c[mi][nj * 2];
                float* c1 = c[mi][nj * 2 + 1];
                mma16816(c0, ah[mi], bh0, bh1);
                mma16816(c0, al[mi], bh0, bh1);
                mma16816(c0, ah[mi], bl0, bl1);
                mma16816(c1, ah[mi], bh2, bh3);
                mma16816(c1, al[mi], bh2, bh3);
                mma16816(c1, ah[mi], bl2, bl3);
            }
        }
    }

    // ---- epilogue ----
#pragma unroll
    for (int mi = 0; mi < 2; ++mi) {
        const int r = m0 + wm * 32 + mi * 16 + (lane >> 2);
#pragma unroll
        for (int nf = 0; nf < 8; ++nf) {
            const int col = wn * 64 + nf * 8 + 2 * (lane & 3) + n0;
            const float b0 = bias[col], b1 = bias[col + 1];
            const float2 v0 = make_float2(c[mi][nf][0] + b0, c[mi][nf][1] + b1);
            const float2 v1 = make_float2(c[mi][nf][2] + b0, c[mi][nf][3] + b1);
            const int b = r >> 10;
            const int n = r & (CN - 1);
            const int h = col >> 6;
            if (slot <= 1) {
                __nv_bfloat16* dh = (slot == 0) ? g_qh : g_kh;
                __nv_bfloat16* dl = (slot == 0) ? g_ql : g_kl;
                uint32_t h0, l0, h1, l1;
                packsplit(v0.x, v0.y, h0, l0);
                packsplit(v1.x, v1.y, h1, l1);
                const size_t i0 = ((size_t)(b * CH + h) * CN + n) * CHD + (col & 63);
                *(uint32_t*)(dh + i0)           = h0;
                *(uint32_t*)(dl + i0)           = l0;
                *(uint32_t*)(dh + i0 + 8 * CHD) = h1;
                *(uint32_t*)(dl + i0 + 8 * CHD) = l1;
            } else {
                const size_t base = ((size_t)(b * CH + h) * CHD + (col & 63)) * CN + n;
                __nv_bfloat16 hh, ll;
                splits(v0.x, hh, ll); g_vth[base] = hh;          g_vtl[base] = ll;
                splits(v0.y, hh, ll); g_vth[base + CN] = hh;     g_vtl[base + CN] = ll;
                splits(v1.x, hh, ll); g_vth[base + 8] = hh;      g_vtl[base + 8] = ll;
                splits(v1.y, hh, ll); g_vth[base + CN + 8] = hh; g_vtl[base + CN + 8] = ll;
            }
        }
    }
}

// ---------------------------------------------------------------------------
// Output GEMM (unchanged from R7).
// ---------------------------------------------------------------------------
constexpr int OAB = 64 * 80;
constexpr int OBB = 128 * 80;

__global__ void __launch_bounds__(256, 2)
gemm_o(const float* __restrict__ bias, float* __restrict__ O)
{
    const __nv_bfloat16* __restrict__ Bg = g_wt + (size_t)3 * CD * CD2;

    __shared__ __align__(16) __nv_bfloat16 As[3 * OAB / 2];
    __shared__ __align__(16) __nv_bfloat16 Bs[3 * OBB / 2];

    const int tid  = threadIdx.x;
    const int wid  = tid >> 5;
    const int lane = tid & 31;
    const int n0   = blockIdx.x * 128;
    const int m0   = blockIdx.y * 64;
    const int wm   = wid & 1;
    const int wn   = wid >> 1;

    const uint32_t as_b = smem_u32(As);
    const uint32_t bs_b = smem_u32(Bs);
    const uint32_t a_base = as_b + (wm * 32 + (lane & 15)) * 80 + (lane >> 4) * 16;
    const uint32_t b_base = bs_b + (wn * 32 + (lane & 7) + ((lane >> 4) << 3)) * 80
                          + ((lane >> 3) & 1) * 16;

    auto issue = [&](int kc, int s) {
        {
            const int row = tid >> 2, sj = (tid & 3) * 16;
            cp16(as_b + s * OAB + row * 80 + sj,
                 (const char*)g_as + (size_t)(m0 + row) * 3072 + kc * 64 + sj);
        }
#pragma unroll
        for (int u = 0; u < 2; ++u) {
            const int e = tid + 256 * u;
            const int row = e >> 2, sj = (e & 3) * 16;
            cp16(bs_b + s * OBB + row * 80 + sj,
                 (const char*)Bg + (size_t)(n0 + row) * 3072 + kc * 64 + sj);
        }
        cp_commit();
    };

    float c[2][4][4];
#pragma unroll
    for (int mi = 0; mi < 2; ++mi)
#pragma unroll
        for (int nf = 0; nf < 4; ++nf)
#pragma unroll
            for (int q = 0; q < 4; ++q) c[mi][nf][q] = 0.f;

    issue(0, 0);
    issue(1, 1);

    for (int kc = 0; kc < 48; ++kc) {
        if (kc < 47) cp_wait1(); else cp_wait0();
        __syncthreads();
        if (kc + 2 < 48) issue(kc + 2, (kc + 2) % 3);
        const uint32_t sa  = (kc % 3) * OAB;
        const uint32_t sbb = (kc % 3) * OBB;

        uint32_t ah[2][4], al[2][4];
#pragma unroll
        for (int mi = 0; mi < 2; ++mi) {
            const uint32_t aa = a_base + sa + mi * 16 * 80;
            ldsm_x4(ah[mi][0], ah[mi][1], ah[mi][2], ah[mi][3], aa);
            ldsm_x4(al[mi][0], al[mi][1], al[mi][2], al[mi][3], aa + 32);
        }
#pragma unroll
        for (int nj = 0; nj < 2; ++nj) {
            const uint32_t bb = b_base + sbb + nj * 16 * 80;
            uint32_t bh0, bh1, bh2, bh3, bl0, bl1, bl2, bl3;
            ldsm_x4(bh0, bh1, bh2, bh3, bb);
            ldsm_x4(bl0, bl1, bl2, bl3, bb + 32);
#pragma unroll
            for (int mi = 0; mi < 2; ++mi) {
                float* c0 = c[mi][nj * 2];
                float* c1 = c[mi][nj * 2 + 1];
                mma16816(c0, ah[mi], bh0, bh1);
                mma16816(c0, al[mi], bh0, bh1);
                mma16816(c0, ah[mi], bl0, bl1);
                mma16816(c1, ah[mi], bh2, bh3);
                mma16816(c1, al[mi], bh2, bh3);
                mma16816(c1, ah[mi], bl2, bl3);
            }
        }
    }

#pragma unroll
    for (int mi = 0; mi < 2; ++mi) {
        const int r = m0 + wm * 32 + mi * 16 + (lane >> 2);
#pragma unroll
        for (int nf = 0; nf < 4; ++nf) {
            const int col = n0 + wn * 32 + nf * 8 + 2 * (lane & 3);
            const float b0 = bias[col], b1 = bias[col + 1];
            *(float2*)(O + (size_t)r * CD + col) =
                make_float2(c[mi][nf][0] + b0, c[mi][nf][1] + b1);
            *(float2*)(O + (size_t)(r + 8) * CD + col) =
                make_float2(c[mi][nf][2] + b0, c[mi][nf][3] + b1);
        }
    }
}

// ---------------------------------------------------------------------------
// Flash attention R8: software-pipelined S(t+1) vs exp/PV(t).
// Dyn smem: Q [0, 34816) | K 4 stages | V 4 stages.  4-stage cp.async,
// one barrier + one wait per tile.  Max-free softmax (unchanged).
// ---------------------------------------------------------------------------
constexpr int QSB = 128 * 272;             // 34816
constexpr int KSB = 32 * 272;              // 8704
constexpr int VSB = 64 * 144;              // 9216
constexpr int ATT_SMEM = QSB + 4 * (KSB + VSB);  // 106496

__global__ void __launch_bounds__(256, 2)
attn_mma_kernel()
{
    extern __shared__ __align__(16) char dsm[];
    const uint32_t qs_b = smem_u32(dsm);
    const uint32_t ks_b = qs_b + QSB;
    const uint32_t vs_b = ks_b + 4 * KSB;

    const int tid  = threadIdx.x;
    const int w    = tid >> 5;
    const int lane = tid & 31;
    const int bh   = blockIdx.y;
    const int q0   = blockIdx.x * 128;
    const int r0   = lane >> 2;
    const int cc   = (lane & 3) * 2;

    const uint32_t a_base = qs_b + (w * 16 + (lane & 15)) * 272 + (lane >> 4) * 16;
    const uint32_t kfrag = ks_b + ((lane & 7) + ((lane >> 4) << 3)) * 272
                         + ((lane >> 3) & 1) * 16;
    const uint32_t vfrag = vs_b + ((lane & 7) + ((lane >> 4) << 3)) * 144
                         + ((lane >> 3) & 1) * 16;
    const size_t qbase = ((size_t)bh * CN + q0) * CHD;
    const size_t kbase = (size_t)bh * CN * CHD;
    const size_t vbase = (size_t)bh * CHD * CN;

    auto issueKV = [&](int kt, int s) {
#pragma unroll
        for (int u = 0; u < 2; ++u) {
            const int e = tid + 256 * u;
            const int row = e >> 4, j = e & 15;
            const __nv_bfloat16* src = (j < 8 ? g_kh : g_kl) + kbase
                                     + (size_t)(kt * 32 + row) * CHD + (j & 7) * 8;
            cp16(ks_b + s * KSB + row * 272 + j * 16, src);
        }
#pragma unroll
        for (int u = 0; u < 2; ++u) {
            const int e = tid + 256 * u;
            const int row = e >> 3, j = e & 7;
            const __nv_bfloat16* src = (j < 4 ? g_vth : g_vtl) + vbase
                                     + (size_t)row * CN + kt * 32 + (j & 3) * 8;
            cp16(vs_b + s * VSB + row * 144 + j * 16, src);
        }
    };

    // S(t) -> dst, reading K stage base sK and Q from smem
    auto computeS = [&](uint32_t sK, float (*dst)[4]) {
#pragma unroll
        for (int f = 0; f < 4; ++f)
#pragma unroll
            for (int q = 0; q < 4; ++q) dst[f][q] = 0.f;
#pragma unroll
        for (int ks = 0; ks < 4; ++ks) {
            uint32_t qh[4], ql[4];
            ldsm_x4(qh[0], qh[1], qh[2], qh[3], a_base + ks * 32);
            ldsm_x4(ql[0], ql[1], ql[2], ql[3], a_base + ks * 32 + 128);
#pragma unroll
            for (int nj = 0; nj < 2; ++nj) {
                const uint32_t bb = kfrag + sK + nj * 16 * 272 + ks * 32;
                uint32_t kh0, kh1, kh2, kh3, kl0, kl1, kl2, kl3;
                ldsm_x4(kh0, kh1, kh2, kh3, bb);
                ldsm_x4(kl0, kl1, kl2, kl3, bb + 128);
                float* s0 = dst[nj * 2];
                float* s1 = dst[nj * 2 + 1];
                mma16816(s0, qh, kh0, kh1);
                mma16816(s0, ql, kh0, kh1);
                mma16816(s0, qh, kl0, kl1);
                mma16816(s1, qh, kh2, kh3);
                mma16816(s1, ql, kh2, kh3);
                mma16816(s1, qh, kl2, kl3);
            }
        }
    };

    float oc[8][4];
#pragma unroll
    for (int f = 0; f < 8; ++f)
#pragma unroll
        for (int q = 0; q < 4; ++q) oc[f][q] = 0.f;
    float lr0 = 0.f, lr1 = 0.f;
    float sc[2][4][4];

    // ---- prologue: stage Q + groups 0..2 ----
    {   // Q: 128 rows x 16 chunks = 2048 cp16 / 256 thr = 8 each
#pragma unroll
        for (int u = 0; u < 8; ++u) {
            const int e = tid + 256 * u;
            const int row = e >> 4, j = e & 15;
            const __nv_bfloat16* src = (j < 8 ? g_qh : g_ql) + qbase
                                     + (size_t)row * CHD + (j & 7) * 8;
            cp16(qs_b + row * 272 + j * 16, src);
        }
        issueKV(0, 0);
        cp_commit();            // c0 = {Q, K0, V0}
        issueKV(1, 1); cp_commit();
        issueKV(2, 2); cp_commit();
    }
    cp_wait2();                 // c0 done
    __syncthreads();
    computeS(0, sc[0]);         // S(0)

#pragma unroll 2
    for (int kt = 0; kt < 32; ++kt) {
        const int cur = kt & 1;
        if (kt < 30) cp_wait1(); else cp_wait0();   // c(kt+1) done
        __syncthreads();
        if (kt <= 28) { issueKV(kt + 3, (kt + 3) & 3); cp_commit(); }

        // ---- S(t+1) first: independent MMAs in flight during softmax ----
        if (kt < 31) computeS(((kt + 1) & 3) * KSB, sc[cur ^ 1]);

        // ---- max-free softmax on sc[cur] ----
        float rs0 = 0.f, rs1 = 0.f;
#pragma unroll
        for (int f = 0; f < 4; ++f) {
            sc[cur][f][0] = __expf(sc[cur][f][0]); rs0 += sc[cur][f][0];
            sc[cur][f][1] = __expf(sc[cur][f][1]); rs0 += sc[cur][f][1];
            sc[cur][f][2] = __expf(sc[cur][f][2]); rs1 += sc[cur][f][2];
            sc[cur][f][3] = __expf(sc[cur][f][3]); rs1 += sc[cur][f][3];
        }
        lr0 += rs0; lr1 += rs1;

        // ---- O += P V ----
        const uint32_t sV = (kt & 3) * VSB;
#pragma unroll
        for (int ks = 0; ks < 2; ++ks) {
            uint32_t ph[4], pl[4];
            packsplit(sc[cur][2 * ks][0],     sc[cur][2 * ks][1],     ph[0], pl[0]);
            packsplit(sc[cur][2 * ks][2],     sc[cur][2 * ks][3],     ph[1], pl[1]);
            packsplit(sc[cur][2 * ks + 1][0], sc[cur][2 * ks + 1][1], ph[2], pl[2]);
            packsplit(sc[cur][2 * ks + 1][2], sc[cur][2 * ks + 1][3], ph[3], pl[3]);
#pragma unroll
            for (int nj = 0; nj < 4; ++nj) {
                const uint32_t bb = vfrag + sV + nj * 16 * 144 + ks * 32;
                uint32_t vh0, vh1, vh2, vh3, vl0, vl1, vl2, vl3;
                ldsm_x4(vh0, vh1, vh2, vh3, bb);
                ldsm_x4(vl0, vl1, vl2, vl3, bb + 64);
                float* o0 = oc[nj * 2];
                float* o1 = oc[nj * 2 + 1];
                mma16816(o0, ph, vh0, vh1);
                mma16816(o0, pl, vh0, vh1);
                mma16816(o0, ph, vl0, vl1);
                mma16816(o1, ph, vh2, vh3);
                mma16816(o1, pl, vh2, vh3);
                mma16816(o1, ph, vl2, vl3);
            }
        }
    }

    // ---- epilogue ----
    lr0 += __shfl_xor_sync(0xffffffffu, lr0, 1);
    lr0 += __shfl_xor_sync(0xffffffffu, lr0, 2);
    lr1 += __shfl_xor_sync(0xffffffffu, lr1, 1);
    lr1 += __shfl_xor_sync(0xffffffffu, lr1, 2);
    const float post = 0.03608439182435161f;   // 1/sqrt(768)
    const float f0 = post / lr0;
    const float f1 = post / lr1;

    const int b = bh / CH;
    const int h = bh % CH;
    const size_t R0 = (size_t)(b * CN + q0 + w * 16 + r0);
#pragma unroll
    for (int j = 0; j < 8; ++j) {
        const int c   = h * 64 + 8 * j + cc;
        const int kc  = c >> 4;
        const int pos = c & 15;
        uint32_t hh, ll;
        packsplit(oc[j][0] * f0, oc[j][1] * f0, hh, ll);
        *(uint32_t*)(g_as + R0 * CD2 + kc * 32 + pos)      = hh;
        *(uint32_t*)(g_as + R0 * CD2 + kc * 32 + pos + 16) = ll;
        packsplit(oc[j][2] * f1, oc[j][3] * f1, hh, ll);
        *(uint32_t*)(g_as + (R0 + 8) * CD2 + kc * 32 + pos)      = hh;
        *(uint32_t*)(g_as + (R0 + 8) * CD2 + kc * 32 + pos + 16) = ll;
    }
}

// ---------------------------------------------------------------------------
extern "C" void kernel_launch(void* const* d_in, const int* in_sizes, int n_in,
                              void* d_out, int out_size)
{
    (void)in_sizes; (void)n_in; (void)out_size;
    const float* x  = (const float*)d_in[0];
    const float* Wq = (const float*)d_in[1];
    const float* bq = (const float*)d_in[2];
    const float* Wk = (const float*)d_in[3];
    const float* bk = (const float*)d_in[4];
    const float* Wv = (const float*)d_in[5];
    const float* bv = (const float*)d_in[6];
    const float* Wo = (const float*)d_in[7];
    const float* bo = (const float*)d_in[8];
    float* out = (float*)d_out;

    cudaFuncSetAttribute(gemm_qkv,
                         cudaFuncAttributeMaxDynamicSharedMemorySize, QKV_SMEM);
    cudaFuncSetAttribute(attn_mma_kernel,
                         cudaFuncAttributeMaxDynamicSharedMemorySize, ATT_SMEM);

    xsplit_kernel<<<CM * (CD / 4) / 256, 256>>>(x);
    wsplit_kernel<<<dim3(24, 24, 4), dim3(32, 8)>>>(Wq, Wk, Wv, Wo);
    gemm_qkv<<<dim3(6, 64, 3), 256, QKV_SMEM>>>(bq, bk, bv);
    attn_mma_kernel<<<dim3(CN / 128, BH), 256, ATT_SMEM>>>();
    gemm_o<<<dim3(6, 128), 256>>>(bo, out);
}